// round 10
// baseline (speedup 1.0000x reference)
#include <cuda_runtime.h>
#include <cuda_bf16.h>
#include <cstdint>

// MultiGridAgentEncoder: fused slot-gather + relu(x @ W + b)
// R10: K-permuted layout. Each gather unit (query u=0, slot s -> u=s+1) owns
// k = 14*u .. 14*u+13 (f=13 zero pad; k=126,127 pad). Producer writes packed
// bf16x2 via STS.32 (7/buffer/unit) instead of 13 STS.16. B built with the
// same permutation, so the consumer GEMM is unchanged.

#define NTHREADS 512
#define GRID     148
#define NTILES   2048
#define PITCH    272          // bytes per K-row (128 bf16 + 16B pad), ldmatrix conflict-free

// smem byte offsets
#define SM_A0_HI 0
#define SM_A0_LO 17408
#define SM_A1_HI 34816
#define SM_A1_LO 52224
#define SM_B_HI  69632        // 256*272 = 69632, ends 139264
#define SM_B_LO  139264       // ends 208896
#define SM_SLOT  208896       // 2 bufs * 8*64 bytes = 1024, ends 209920
#define SMEM_BYTES 209920

// Pre-split W (filled once by w_split): [n][k_new] bf16
__device__ __nv_bfloat16 g_Whi[256 * 128];
__device__ __nv_bfloat16 g_Wlo[256 * 128];

// K permutation: k_new = 14*u + f. u=0: query f (0..12). u=1..8: slot u-1,
// feature f, k_old = 13 + 13*(u-1) + f. f==13 or k_new>=126 -> zero.
__global__ void w_split(const float* __restrict__ W) {
    const int kn = blockIdx.x;       // 0..127
    const int n = threadIdx.x;       // 0..255
    float w = 0.0f;
    if (kn < 126) {
        const int u = kn / 14, f = kn % 14;
        if (f < 13) {
            const int ko = (u == 0) ? f : 13 + 13 * (u - 1) + f;
            w = W[ko * 256 + n];
        }
    }
    __nv_bfloat16 h = __float2bfloat16(w);
    g_Whi[n * 128 + kn] = h;
    g_Wlo[n * 128 + kn] = __float2bfloat16(w - __bfloat162float(h));
}

static __device__ __forceinline__ uint32_t smem_u32(const void* p) {
    uint32_t a;
    asm("{ .reg .u64 t; cvta.to.shared.u64 t, %1; cvt.u32.u64 %0, t; }" : "=r"(a) : "l"(p));
    return a;
}
static __device__ __forceinline__ void bar_sync(int id, int cnt) {
    asm volatile("bar.sync %0, %1;" :: "r"(id), "r"(cnt) : "memory");
}
static __device__ __forceinline__ void bar_arrive(int id, int cnt) {
    asm volatile("bar.arrive %0, %1;" :: "r"(id), "r"(cnt) : "memory");
}
static __device__ __forceinline__ void ldsm_x4(uint32_t& r0, uint32_t& r1, uint32_t& r2,
                                               uint32_t& r3, uint32_t addr) {
    asm volatile("ldmatrix.sync.aligned.m8n8.x4.shared.b16 {%0,%1,%2,%3}, [%4];"
                 : "=r"(r0), "=r"(r1), "=r"(r2), "=r"(r3) : "r"(addr));
}
static __device__ __forceinline__ void mma_bf16(float* c, const uint32_t* a,
                                                uint32_t b0, uint32_t b1) {
    asm volatile(
        "mma.sync.aligned.m16n8k16.row.col.f32.bf16.bf16.f32 "
        "{%0,%1,%2,%3}, {%4,%5,%6,%7}, {%8,%9}, {%0,%1,%2,%3};"
        : "+f"(c[0]), "+f"(c[1]), "+f"(c[2]), "+f"(c[3])
        : "r"(a[0]), "r"(a[1]), "r"(a[2]), "r"(a[3]), "r"(b0), "r"(b1));
}
// pack two floats to bf16x2 (lo = v0, hi = v1)
static __device__ __forceinline__ uint32_t cvt2(float v0, float v1) {
    uint32_t r;
    asm("cvt.rn.bf16x2.f32 %0, %1, %2;" : "=r"(r) : "f"(v1), "f"(v0));
    return r;
}
// write 13 features (hi/lo split, packed STS.32) at 4-aligned k0*2 (k0 = 14*u)
static __device__ __forceinline__ void write14(char* ah, char* al, int k0, const float* f) {
#pragma unroll
    for (int p = 0; p < 7; p++) {
        const float v0 = f[2 * p];
        const float v1 = (2 * p + 1 < 13) ? f[2 * p + 1] : 0.0f;
        const uint32_t h = cvt2(v0, v1);
        const float l0 = v0 - __uint_as_float(h << 16);
        const float l1 = v1 - __uint_as_float(h & 0xffff0000u);
        const uint32_t l = cvt2(l0, l1);
        *(uint32_t*)(ah + k0 * 2 + p * 4) = h;
        *(uint32_t*)(al + k0 * 2 + p * 4) = l;
    }
}

__global__ __launch_bounds__(512, 1)
void mg_enc_ws(const float* __restrict__ qpos, const float* __restrict__ qdir,
               const float* __restrict__ qab,  const float* __restrict__ qcar,
               const float* __restrict__ qst,
               const float* __restrict__ apos, const float* __restrict__ adir,
               const float* __restrict__ aab,  const float* __restrict__ acar,
               const float* __restrict__ ast,
               const int*   __restrict__ color,
               const float* __restrict__ bias,
               float* __restrict__ out)
{
    extern __shared__ __align__(128) char smem[];
    const uint32_t sbase = smem_u32(smem);
    const int tid = threadIdx.x;

    if (tid >= 256) {
        // ======================= PRODUCER (warps 8..15) =======================
        const int tp = tid - 256;

        // zero-pad K rows 126,127 in all 4 A buffers (once; f=13 pads are
        // rewritten every tile by write14)
        if (tp < 128) {
            const int r = tp >> 1, kk = 126 + (tp & 1);
            const uint32_t o = r * PITCH + kk * 2;
            *(__nv_bfloat16*)(smem + SM_A0_HI + o) = __nv_bfloat16(0.0f);
            *(__nv_bfloat16*)(smem + SM_A0_LO + o) = __nv_bfloat16(0.0f);
            *(__nv_bfloat16*)(smem + SM_A1_HI + o) = __nv_bfloat16(0.0f);
            *(__nv_bfloat16*)(smem + SM_A1_LO + o) = __nv_bfloat16(0.0f);
        }

        int t = blockIdx.x;
        int4 c0, c1, c2, c3;
        if (tp < 64) {
            const int4* cp = (const int4*)(color + (size_t)(t * 64 + tp) * 16);
            c0 = cp[0]; c1 = cp[1]; c2 = cp[2]; c3 = cp[3];
        }

        for (int it = 0; t < NTILES; it++, t += GRID) {
            const int buf = it & 1;
            if (it >= 2) bar_sync(3 + buf, 512);              // wait buf free

            signed char* slotb = (signed char*)(smem + SM_SLOT) + buf * 512;
            if (tp < 64) {
                int cols[16] = { c0.x, c0.y, c0.z, c0.w, c1.x, c1.y, c1.z, c1.w,
                                 c2.x, c2.y, c2.z, c2.w, c3.x, c3.y, c3.z, c3.w };
                signed char sa[8];
#pragma unroll
                for (int s = 0; s < 8; s++) sa[s] = -1;
                int sg = 0, sy = 0;
#pragma unroll
                for (int n = 0; n < 16; n++) {
                    int c = cols[n];
                    if (c == 5) { if (sg < 4) sa[sg] = (signed char)n; sg++; }
                    else if (c == 4) { if (sy < 4) sa[4 + sy] = (signed char)n; sy++; }
                }
#pragma unroll
                for (int s = 0; s < 8; s++) slotb[s * 64 + tp] = sa[s];
            }
            bar_sync(5, 256);                                  // producers: slots visible

            // prefetch next tile's color rows
            const int tn = t + GRID;
            if (tp < 64 && tn < NTILES) {
                const int4* cp = (const int4*)(color + (size_t)(tn * 64 + tp) * 16);
                c0 = cp[0]; c1 = cp[1]; c2 = cp[2]; c3 = cp[3];
            }

            char* const ahB = smem + (buf ? SM_A1_HI : SM_A0_HI);
            char* const alB = smem + (buf ? SM_A1_LO : SM_A0_LO);
            const int row0 = t * 64;

            // query features -> unit 0 (k 0..12), 64 threads one per row
            if (tp < 64) {
                const size_t row = (size_t)(row0 + tp);
                float f[13];
                *(float2*)(f + 0) = *(const float2*)(qpos + row * 2);
                *(float4*)(f + 2) = *(const float4*)(qdir + row * 4);
                *(float2*)(f + 6) = *(const float2*)(qab  + row * 2);
                *(float2*)(f + 8) = *(const float2*)(qcar + row * 2);
                f[10] = qst[row * 3 + 0]; f[11] = qst[row * 3 + 1]; f[12] = qst[row * 3 + 2];
                write14(ahB + tp * PITCH, alB + tp * PITCH, 0, f);
            }

            // agent gather: unit = (row, slot) -> k range 14*(s+1); 2 units/thread
#pragma unroll
            for (int uu = 0; uu < 2; uu++) {
                const int u = tp * 2 + uu;
                const int r = u >> 3, s = u & 7;
                const int a = (int)slotb[s * 64 + r];
                float f[13];
                if (a >= 0) {
                    const size_t base = (size_t)(row0 + r) * 16 + a;
                    *(float2*)(f + 0) = *(const float2*)(apos + base * 2);
                    *(float4*)(f + 2) = *(const float4*)(adir + base * 4);
                    *(float2*)(f + 6) = *(const float2*)(aab  + base * 2);
                    *(float2*)(f + 8) = *(const float2*)(acar + base * 2);
                    f[10] = ast[base * 3 + 0]; f[11] = ast[base * 3 + 1]; f[12] = ast[base * 3 + 2];
                } else {
#pragma unroll
                    for (int j = 0; j < 13; j++) f[j] = 0.0f;
                }
                write14(ahB + r * PITCH, alB + r * PITCH, 14 * (s + 1), f);
            }
            bar_arrive(1 + buf, 512);                          // A[buf] ready
        }
    } else {
        // ======================= CONSUMER (warps 0..7) =======================
        const int wid = tid >> 5, lid = tid & 31;

        // B tiles: copy pre-split bf16 W into smem (once)
#pragma unroll
        for (int it = 0; it < 16; it++) {
            const int idx = it * 256 + tid;
            const int n = idx >> 4, c = idx & 15;
            *(uint4*)(smem + SM_B_HI + n * PITCH + c * 16) =
                *(const uint4*)((const char*)g_Whi + n * 256 + c * 16);
            *(uint4*)(smem + SM_B_LO + n * PITCH + c * 16) =
                *(const uint4*)((const char*)g_Wlo + n * 256 + c * 16);
        }

        const int wm = wid >> 2, wn = wid & 3;   // 2 x 4 warp grid, warp tile 32x64
        const uint32_t lrow = lid & 15, lhalf = (uint32_t)lid >> 4;
        const uint32_t a_lane = (wm * 32 + lrow) * PITCH + lhalf * 16;
        const uint32_t b_lane = (wn * 64 + lrow) * PITCH + lhalf * 16;
        const uint32_t BHb = sbase + SM_B_HI + b_lane;
        const uint32_t BLb = sbase + SM_B_LO + b_lane;

        float be[8], bo[8];
#pragma unroll
        for (int nt = 0; nt < 8; nt++) {
            const int c = wn * 64 + (lid & 3) * 2 + nt * 8;
            be[nt] = bias[c];
            bo[nt] = bias[c + 1];
        }

        int t = blockIdx.x;
        for (int it = 0; t < NTILES; it++, t += GRID) {
            const int buf = it & 1;
            bar_sync(1 + buf, 512);                            // wait A[buf] ready

            const uint32_t AHb = sbase + (buf ? SM_A1_HI : SM_A0_HI) + a_lane;
            const uint32_t ALb = sbase + (buf ? SM_A1_LO : SM_A0_LO) + a_lane;

            float acc[2][8][4];
#pragma unroll
            for (int mt = 0; mt < 2; mt++)
#pragma unroll
                for (int nt = 0; nt < 8; nt++)
#pragma unroll
                    for (int e = 0; e < 4; e++) acc[mt][nt][e] = 0.0f;

            // merged k-loop: AH,BH -> AH*BH ; AL -> AL*BH ; BL (reuse) -> AH*BL
#pragma unroll 2
            for (int ks = 0; ks < 8; ks++) {
                const uint32_t koff = ks * 32;
                uint32_t ah[2][4], al[2][4], b[4][4];
#pragma unroll
                for (int mt = 0; mt < 2; mt++)
                    ldsm_x4(ah[mt][0], ah[mt][1], ah[mt][2], ah[mt][3],
                            AHb + mt * (16 * PITCH) + koff);
#pragma unroll
                for (int nb = 0; nb < 4; nb++)
                    ldsm_x4(b[nb][0], b[nb][1], b[nb][2], b[nb][3],
                            BHb + nb * (16 * PITCH) + koff);
#pragma unroll
                for (int mt = 0; mt < 2; mt++)
#pragma unroll
                    for (int nb = 0; nb < 4; nb++) {
                        mma_bf16(acc[mt][nb * 2 + 0], ah[mt], b[nb][0], b[nb][2]);
                        mma_bf16(acc[mt][nb * 2 + 1], ah[mt], b[nb][1], b[nb][3]);
                    }
#pragma unroll
                for (int mt = 0; mt < 2; mt++)
                    ldsm_x4(al[mt][0], al[mt][1], al[mt][2], al[mt][3],
                            ALb + mt * (16 * PITCH) + koff);
#pragma unroll
                for (int mt = 0; mt < 2; mt++)
#pragma unroll
                    for (int nb = 0; nb < 4; nb++) {
                        mma_bf16(acc[mt][nb * 2 + 0], al[mt], b[nb][0], b[nb][2]);
                        mma_bf16(acc[mt][nb * 2 + 1], al[mt], b[nb][1], b[nb][3]);
                    }
#pragma unroll
                for (int nb = 0; nb < 4; nb++)
                    ldsm_x4(b[nb][0], b[nb][1], b[nb][2], b[nb][3],
                            BLb + nb * (16 * PITCH) + koff);
#pragma unroll
                for (int mt = 0; mt < 2; mt++)
#pragma unroll
                    for (int nb = 0; nb < 4; nb++) {
                        mma_bf16(acc[mt][nb * 2 + 0], ah[mt], b[nb][0], b[nb][2]);
                        mma_bf16(acc[mt][nb * 2 + 1], ah[mt], b[nb][1], b[nb][3]);
                    }
            }
            bar_arrive(3 + buf, 512);                          // A[buf] free

            // epilogue: bias + relu + direct float2 stores (overlaps producer)
            const int rbase = t * 64 + wm * 32 + (lid >> 2);
            const int cbase = wn * 64 + (lid & 3) * 2;
#pragma unroll
            for (int mt = 0; mt < 2; mt++) {
#pragma unroll
                for (int nt = 0; nt < 8; nt++) {
                    const int c = cbase + nt * 8;
                    float2 v0, v1;
                    v0.x = fmaxf(acc[mt][nt][0] + be[nt], 0.0f);
                    v0.y = fmaxf(acc[mt][nt][1] + bo[nt], 0.0f);
                    v1.x = fmaxf(acc[mt][nt][2] + be[nt], 0.0f);
                    v1.y = fmaxf(acc[mt][nt][3] + bo[nt], 0.0f);
                    const size_t r0 = (size_t)(rbase + mt * 16);
                    *(float2*)(out + r0 * 256 + c)       = v0;
                    *(float2*)(out + (r0 + 8) * 256 + c) = v1;
                }
            }
        }
    }
}

extern "C" void kernel_launch(void* const* d_in, const int* in_sizes, int n_in,
                              void* d_out, int out_size)
{
    const float* qpos  = (const float*)d_in[0];
    const float* qdir  = (const float*)d_in[1];
    const float* qab   = (const float*)d_in[2];
    const float* qcar  = (const float*)d_in[3];
    const float* qst   = (const float*)d_in[4];
    const float* apos  = (const float*)d_in[5];
    const float* adir  = (const float*)d_in[6];
    const float* aab   = (const float*)d_in[7];
    const float* acar  = (const float*)d_in[8];
    const float* ast   = (const float*)d_in[9];
    const int*   color = (const int*)  d_in[10];
    const float* W     = (const float*)d_in[11];
    const float* bias  = (const float*)d_in[12];
    float* out = (float*)d_out;

    w_split<<<128, 256>>>(W);

    cudaFuncSetAttribute(mg_enc_ws,
                         cudaFuncAttributeMaxDynamicSharedMemorySize, SMEM_BYTES);
    mg_enc_ws<<<GRID, NTHREADS, SMEM_BYTES>>>(
        qpos, qdir, qab, qcar, qst,
        apos, adir, aab, acar, ast,
        color, bias, out);
}

// round 11
// speedup vs baseline: 1.0268x; 1.0268x over previous
#include <cuda_runtime.h>
#include <cuda_bf16.h>
#include <cstdint>

// MultiGridAgentEncoder: fused slot-gather + relu(x @ W + b)
// R11: producer loads ALL agent features coalesced into registers (no slot
// dependency), scatters via inverse agent->slot map; empty slots zero-filled
// by slot threads. Consumer = R10 merged split-bf16 HMMA, K-permuted layout.

#define NTHREADS 512
#define GRID     148
#define NTILES   2048
#define PITCH    272          // bytes per K-row (128 bf16 + 16B pad)

// smem byte offsets
#define SM_A0_HI 0
#define SM_A0_LO 17408
#define SM_A1_HI 34816
#define SM_A1_LO 52224
#define SM_B_HI  69632        // 256*272 = 69632, ends 139264
#define SM_B_LO  139264       // ends 208896
#define SM_INV   208896       // 2 bufs * 64 rows * 16B = 2048, ends 210944
#define SMEM_BYTES 210944

// Pre-split W (filled once by w_split): [n][k_new] bf16
__device__ __nv_bfloat16 g_Whi[256 * 128];
__device__ __nv_bfloat16 g_Wlo[256 * 128];

// K permutation: k_new = 14*u + f. u=0: query f (0..12). u=1..8: slot u-1,
// feature f, k_old = 13 + 13*(u-1) + f. f==13 or k_new>=126 -> zero.
__global__ void w_split(const float* __restrict__ W) {
    const int kn = blockIdx.x;       // 0..127
    const int n = threadIdx.x;       // 0..255
    float w = 0.0f;
    if (kn < 126) {
        const int u = kn / 14, f = kn % 14;
        if (f < 13) {
            const int ko = (u == 0) ? f : 13 + 13 * (u - 1) + f;
            w = W[ko * 256 + n];
        }
    }
    __nv_bfloat16 h = __float2bfloat16(w);
    g_Whi[n * 128 + kn] = h;
    g_Wlo[n * 128 + kn] = __float2bfloat16(w - __bfloat162float(h));
}

static __device__ __forceinline__ uint32_t smem_u32(const void* p) {
    uint32_t a;
    asm("{ .reg .u64 t; cvta.to.shared.u64 t, %1; cvt.u32.u64 %0, t; }" : "=r"(a) : "l"(p));
    return a;
}
static __device__ __forceinline__ void bar_sync(int id, int cnt) {
    asm volatile("bar.sync %0, %1;" :: "r"(id), "r"(cnt) : "memory");
}
static __device__ __forceinline__ void bar_arrive(int id, int cnt) {
    asm volatile("bar.arrive %0, %1;" :: "r"(id), "r"(cnt) : "memory");
}
static __device__ __forceinline__ void ldsm_x4(uint32_t& r0, uint32_t& r1, uint32_t& r2,
                                               uint32_t& r3, uint32_t addr) {
    asm volatile("ldmatrix.sync.aligned.m8n8.x4.shared.b16 {%0,%1,%2,%3}, [%4];"
                 : "=r"(r0), "=r"(r1), "=r"(r2), "=r"(r3) : "r"(addr));
}
static __device__ __forceinline__ void mma_bf16(float* c, const uint32_t* a,
                                                uint32_t b0, uint32_t b1) {
    asm volatile(
        "mma.sync.aligned.m16n8k16.row.col.f32.bf16.bf16.f32 "
        "{%0,%1,%2,%3}, {%4,%5,%6,%7}, {%8,%9}, {%0,%1,%2,%3};"
        : "+f"(c[0]), "+f"(c[1]), "+f"(c[2]), "+f"(c[3])
        : "r"(a[0]), "r"(a[1]), "r"(a[2]), "r"(a[3]), "r"(b0), "r"(b1));
}
// pack two floats to bf16x2 (lo = v0, hi = v1)
static __device__ __forceinline__ uint32_t cvt2(float v0, float v1) {
    uint32_t r;
    asm("cvt.rn.bf16x2.f32 %0, %1, %2;" : "=r"(r) : "f"(v1), "f"(v0));
    return r;
}
// write 13 features (hi/lo split, packed STS.32) at 4-aligned k0*2 (k0 = 14*u)
static __device__ __forceinline__ void write14(char* ah, char* al, int k0, const float* f) {
#pragma unroll
    for (int p = 0; p < 7; p++) {
        const float v0 = f[2 * p];
        const float v1 = (2 * p + 1 < 13) ? f[2 * p + 1] : 0.0f;
        const uint32_t h = cvt2(v0, v1);
        const float l0 = v0 - __uint_as_float(h << 16);
        const float l1 = v1 - __uint_as_float(h & 0xffff0000u);
        const uint32_t l = cvt2(l0, l1);
        *(uint32_t*)(ah + k0 * 2 + p * 4) = h;
        *(uint32_t*)(al + k0 * 2 + p * 4) = l;
    }
}

__global__ __launch_bounds__(512, 1)
void mg_enc_ws(const float* __restrict__ qpos, const float* __restrict__ qdir,
               const float* __restrict__ qab,  const float* __restrict__ qcar,
               const float* __restrict__ qst,
               const float* __restrict__ apos, const float* __restrict__ adir,
               const float* __restrict__ aab,  const float* __restrict__ acar,
               const float* __restrict__ ast,
               const int*   __restrict__ color,
               const float* __restrict__ bias,
               float* __restrict__ out)
{
    extern __shared__ __align__(128) char smem[];
    const uint32_t sbase = smem_u32(smem);
    const int tid = threadIdx.x;

    if (tid >= 256) {
        // ======================= PRODUCER (warps 8..15) =======================
        const int tp = tid - 256;
        const int fr = tp >> 2, fp = tp & 3;    // feature duty: row fr, agents 4fp..4fp+3

        // zero-pad K rows 126,127 in all 4 A buffers (once)
        if (tp < 128) {
            const int r = tp >> 1, kk = 126 + (tp & 1);
            const uint32_t o = r * PITCH + kk * 2;
            *(__nv_bfloat16*)(smem + SM_A0_HI + o) = __nv_bfloat16(0.0f);
            *(__nv_bfloat16*)(smem + SM_A0_LO + o) = __nv_bfloat16(0.0f);
            *(__nv_bfloat16*)(smem + SM_A1_HI + o) = __nv_bfloat16(0.0f);
            *(__nv_bfloat16*)(smem + SM_A1_LO + o) = __nv_bfloat16(0.0f);
        }

        int t = blockIdx.x;
        int4 c0, c1, c2, c3;
        if (tp < 64) {
            const int4* cp = (const int4*)(color + (size_t)(t * 64 + tp) * 16);
            c0 = cp[0]; c1 = cp[1]; c2 = cp[2]; c3 = cp[3];
        }

        for (int it = 0; t < NTILES; it++, t += GRID) {
            const int buf = it & 1;
            const int row0 = t * 64;

            // ---- coalesced feature loads for current tile (issue before waits) ----
            const size_t frow = (size_t)(row0 + fr);
            const float4 ap0 = *(const float4*)(apos + frow * 32 + fp * 8);
            const float4 ap1 = *(const float4*)(apos + frow * 32 + fp * 8 + 4);
            const float4 ad0 = *(const float4*)(adir + frow * 64 + fp * 16);
            const float4 ad1 = *(const float4*)(adir + frow * 64 + fp * 16 + 4);
            const float4 ad2 = *(const float4*)(adir + frow * 64 + fp * 16 + 8);
            const float4 ad3 = *(const float4*)(adir + frow * 64 + fp * 16 + 12);
            const float4 ab0 = *(const float4*)(aab  + frow * 32 + fp * 8);
            const float4 ab1 = *(const float4*)(aab  + frow * 32 + fp * 8 + 4);
            const float4 ac0 = *(const float4*)(acar + frow * 32 + fp * 8);
            const float4 ac1 = *(const float4*)(acar + frow * 32 + fp * 8 + 4);
            const float4 as0 = *(const float4*)(ast  + frow * 48 + fp * 12);
            const float4 as1 = *(const float4*)(ast  + frow * 48 + fp * 12 + 4);
            const float4 as2 = *(const float4*)(ast  + frow * 48 + fp * 12 + 8);

            // query loads (tp<64, row tp)
            float q[13];
            if (tp < 64) {
                const size_t row = (size_t)(row0 + tp);
                *(float2*)(q + 0) = *(const float2*)(qpos + row * 2);
                *(float4*)(q + 2) = *(const float4*)(qdir + row * 4);
                *(float2*)(q + 6) = *(const float2*)(qab  + row * 2);
                *(float2*)(q + 8) = *(const float2*)(qcar + row * 2);
                q[10] = qst[row * 3 + 0]; q[11] = qst[row * 3 + 1]; q[12] = qst[row * 3 + 2];
            }

            // ---- slot compute (regs only): inverse map + fill counts ----
            uint32_t invw[4] = {0xFFFFFFFFu, 0xFFFFFFFFu, 0xFFFFFFFFu, 0xFFFFFFFFu};
            int sg = 0, sy = 0;
            if (tp < 64) {
                int cols[16] = { c0.x, c0.y, c0.z, c0.w, c1.x, c1.y, c1.z, c1.w,
                                 c2.x, c2.y, c2.z, c2.w, c3.x, c3.y, c3.z, c3.w };
#pragma unroll
                for (int n = 0; n < 16; n++) {
                    const int c = cols[n];
                    int s = -1;
                    if (c == 5) { if (sg < 4) s = sg; sg++; }
                    else if (c == 4) { if (sy < 4) s = 4 + sy; sy++; }
                    if (s >= 0) {
                        invw[n >> 2] &= ~(0xFFu << (8 * (n & 3)));
                        invw[n >> 2] |= (uint32_t)s << (8 * (n & 3));
                    }
                }
            }

            if (it >= 2) bar_sync(3 + buf, 512);              // wait buf free

            // store inverse map (16B per row)
            if (tp < 64)
                *(uint4*)(smem + SM_INV + buf * 1024 + tp * 16) =
                    make_uint4(invw[0], invw[1], invw[2], invw[3]);
            bar_sync(5, 256);                                  // inv visible to producers

            // prefetch next tile's color rows
            const int tn = t + GRID;
            if (tp < 64 && tn < NTILES) {
                const int4* cp = (const int4*)(color + (size_t)(tn * 64 + tp) * 16);
                c0 = cp[0]; c1 = cp[1]; c2 = cp[2]; c3 = cp[3];
            }

            char* const ahB = smem + (buf ? SM_A1_HI : SM_A0_HI);
            char* const alB = smem + (buf ? SM_A1_LO : SM_A0_LO);

            // slot threads: query unit + zero-fill empty slots (disjoint from agents)
            if (tp < 64) {
                char* ah = ahB + tp * PITCH;
                char* al = alB + tp * PITCH;
                write14(ah, al, 0, q);
#pragma unroll
                for (int s = 0; s < 8; s++) {
                    const bool empty = (s < 4) ? (s >= sg) : (s - 4 >= sy);
                    if (empty) {
                        const int k0 = 14 * (s + 1);
#pragma unroll
                        for (int p7 = 0; p7 < 7; p7++) {
                            *(uint32_t*)(ah + k0 * 2 + p7 * 4) = 0u;
                            *(uint32_t*)(al + k0 * 2 + p7 * 4) = 0u;
                        }
                    }
                }
            }

            // agent scatter from registers via inverse map
            {
                float fa[4][13];
                fa[0][0]=ap0.x; fa[0][1]=ap0.y; fa[1][0]=ap0.z; fa[1][1]=ap0.w;
                fa[2][0]=ap1.x; fa[2][1]=ap1.y; fa[3][0]=ap1.z; fa[3][1]=ap1.w;
                fa[0][2]=ad0.x; fa[0][3]=ad0.y; fa[0][4]=ad0.z; fa[0][5]=ad0.w;
                fa[1][2]=ad1.x; fa[1][3]=ad1.y; fa[1][4]=ad1.z; fa[1][5]=ad1.w;
                fa[2][2]=ad2.x; fa[2][3]=ad2.y; fa[2][4]=ad2.z; fa[2][5]=ad2.w;
                fa[3][2]=ad3.x; fa[3][3]=ad3.y; fa[3][4]=ad3.z; fa[3][5]=ad3.w;
                fa[0][6]=ab0.x; fa[0][7]=ab0.y; fa[1][6]=ab0.z; fa[1][7]=ab0.w;
                fa[2][6]=ab1.x; fa[2][7]=ab1.y; fa[3][6]=ab1.z; fa[3][7]=ab1.w;
                fa[0][8]=ac0.x; fa[0][9]=ac0.y; fa[1][8]=ac0.z; fa[1][9]=ac0.w;
                fa[2][8]=ac1.x; fa[2][9]=ac1.y; fa[3][8]=ac1.z; fa[3][9]=ac1.w;
                fa[0][10]=as0.x; fa[0][11]=as0.y; fa[0][12]=as0.z;
                fa[1][10]=as0.w; fa[1][11]=as1.x; fa[1][12]=as1.y;
                fa[2][10]=as1.z; fa[2][11]=as1.w; fa[2][12]=as2.x;
                fa[3][10]=as2.y; fa[3][11]=as2.z; fa[3][12]=as2.w;

                const uint32_t iw =
                    *(const uint32_t*)(smem + SM_INV + buf * 1024 + fr * 16 + fp * 4);
                char* ah = ahB + fr * PITCH;
                char* al = alB + fr * PITCH;
#pragma unroll
                for (int i = 0; i < 4; i++) {
                    const uint32_t b = (iw >> (8 * i)) & 0xFFu;
                    if (b != 0xFFu)
                        write14(ah, al, 14 * ((int)b + 1), fa[i]);
                }
            }
            bar_arrive(1 + buf, 512);                          // A[buf] ready
        }
    } else {
        // ======================= CONSUMER (warps 0..7) =======================
        const int wid = tid >> 5, lid = tid & 31;

        // B tiles: copy pre-split bf16 W into smem (once)
#pragma unroll
        for (int it = 0; it < 16; it++) {
            const int idx = it * 256 + tid;
            const int n = idx >> 4, c = idx & 15;
            *(uint4*)(smem + SM_B_HI + n * PITCH + c * 16) =
                *(const uint4*)((const char*)g_Whi + n * 256 + c * 16);
            *(uint4*)(smem + SM_B_LO + n * PITCH + c * 16) =
                *(const uint4*)((const char*)g_Wlo + n * 256 + c * 16);
        }

        const int wm = wid >> 2, wn = wid & 3;   // 2 x 4 warp grid, warp tile 32x64
        const uint32_t lrow = lid & 15, lhalf = (uint32_t)lid >> 4;
        const uint32_t a_lane = (wm * 32 + lrow) * PITCH + lhalf * 16;
        const uint32_t b_lane = (wn * 64 + lrow) * PITCH + lhalf * 16;
        const uint32_t BHb = sbase + SM_B_HI + b_lane;
        const uint32_t BLb = sbase + SM_B_LO + b_lane;

        float be[8], bo[8];
#pragma unroll
        for (int nt = 0; nt < 8; nt++) {
            const int c = wn * 64 + (lid & 3) * 2 + nt * 8;
            be[nt] = bias[c];
            bo[nt] = bias[c + 1];
        }

        int t = blockIdx.x;
        for (int it = 0; t < NTILES; it++, t += GRID) {
            const int buf = it & 1;
            bar_sync(1 + buf, 512);                            // wait A[buf] ready

            const uint32_t AHb = sbase + (buf ? SM_A1_HI : SM_A0_HI) + a_lane;
            const uint32_t ALb = sbase + (buf ? SM_A1_LO : SM_A0_LO) + a_lane;

            float acc[2][8][4];
#pragma unroll
            for (int mt = 0; mt < 2; mt++)
#pragma unroll
                for (int nt = 0; nt < 8; nt++)
#pragma unroll
                    for (int e = 0; e < 4; e++) acc[mt][nt][e] = 0.0f;

            // merged k-loop: AH,BH -> AH*BH ; AL -> AL*BH ; BL (reuse) -> AH*BL
#pragma unroll 2
            for (int ks = 0; ks < 8; ks++) {
                const uint32_t koff = ks * 32;
                uint32_t ah[2][4], al[2][4], b[4][4];
#pragma unroll
                for (int mt = 0; mt < 2; mt++)
                    ldsm_x4(ah[mt][0], ah[mt][1], ah[mt][2], ah[mt][3],
                            AHb + mt * (16 * PITCH) + koff);
#pragma unroll
                for (int nb = 0; nb < 4; nb++)
                    ldsm_x4(b[nb][0], b[nb][1], b[nb][2], b[nb][3],
                            BHb + nb * (16 * PITCH) + koff);
#pragma unroll
                for (int mt = 0; mt < 2; mt++)
#pragma unroll
                    for (int nb = 0; nb < 4; nb++) {
                        mma_bf16(acc[mt][nb * 2 + 0], ah[mt], b[nb][0], b[nb][2]);
                        mma_bf16(acc[mt][nb * 2 + 1], ah[mt], b[nb][1], b[nb][3]);
                    }
#pragma unroll
                for (int mt = 0; mt < 2; mt++)
                    ldsm_x4(al[mt][0], al[mt][1], al[mt][2], al[mt][3],
                            ALb + mt * (16 * PITCH) + koff);
#pragma unroll
                for (int mt = 0; mt < 2; mt++)
#pragma unroll
                    for (int nb = 0; nb < 4; nb++) {
                        mma_bf16(acc[mt][nb * 2 + 0], al[mt], b[nb][0], b[nb][2]);
                        mma_bf16(acc[mt][nb * 2 + 1], al[mt], b[nb][1], b[nb][3]);
                    }
#pragma unroll
                for (int nb = 0; nb < 4; nb++)
                    ldsm_x4(b[nb][0], b[nb][1], b[nb][2], b[nb][3],
                            BLb + nb * (16 * PITCH) + koff);
#pragma unroll
                for (int mt = 0; mt < 2; mt++)
#pragma unroll
                    for (int nb = 0; nb < 4; nb++) {
                        mma_bf16(acc[mt][nb * 2 + 0], ah[mt], b[nb][0], b[nb][2]);
                        mma_bf16(acc[mt][nb * 2 + 1], ah[mt], b[nb][1], b[nb][3]);
                    }
            }
            bar_arrive(3 + buf, 512);                          // A[buf] free

            // epilogue: bias + relu + direct float2 stores (overlaps producer)
            const int rbase = t * 64 + wm * 32 + (lid >> 2);
            const int cbase = wn * 64 + (lid & 3) * 2;
#pragma unroll
            for (int mt = 0; mt < 2; mt++) {
#pragma unroll
                for (int nt = 0; nt < 8; nt++) {
                    const int c = cbase + nt * 8;
                    float2 v0, v1;
                    v0.x = fmaxf(acc[mt][nt][0] + be[nt], 0.0f);
                    v0.y = fmaxf(acc[mt][nt][1] + bo[nt], 0.0f);
                    v1.x = fmaxf(acc[mt][nt][2] + be[nt], 0.0f);
                    v1.y = fmaxf(acc[mt][nt][3] + bo[nt], 0.0f);
                    const size_t r0 = (size_t)(rbase + mt * 16);
                    *(float2*)(out + r0 * 256 + c)       = v0;
                    *(float2*)(out + (r0 + 8) * 256 + c) = v1;
                }
            }
        }
    }
}

extern "C" void kernel_launch(void* const* d_in, const int* in_sizes, int n_in,
                              void* d_out, int out_size)
{
    const float* qpos  = (const float*)d_in[0];
    const float* qdir  = (const float*)d_in[1];
    const float* qab   = (const float*)d_in[2];
    const float* qcar  = (const float*)d_in[3];
    const float* qst   = (const float*)d_in[4];
    const float* apos  = (const float*)d_in[5];
    const float* adir  = (const float*)d_in[6];
    const float* aab   = (const float*)d_in[7];
    const float* acar  = (const float*)d_in[8];
    const float* ast   = (const float*)d_in[9];
    const int*   color = (const int*)  d_in[10];
    const float* W     = (const float*)d_in[11];
    const float* bias  = (const float*)d_in[12];
    float* out = (float*)d_out;

    w_split<<<128, 256>>>(W);

    cudaFuncSetAttribute(mg_enc_ws,
                         cudaFuncAttributeMaxDynamicSharedMemorySize, SMEM_BYTES);
    mg_enc_ws<<<GRID, NTHREADS, SMEM_BYTES>>>(
        qpos, qdir, qab, qcar, qst,
        apos, adir, aab, acar, ast,
        color, bias, out);
}

// round 15
// speedup vs baseline: 1.2613x; 1.2285x over previous
#include <cuda_runtime.h>
#include <cuda_fp16.h>
#include <cstdint>

// MultiGridAgentEncoder: fused slot-gather + relu(x @ W + b)
// R12: fp16 2-pass scheme. A = fp16(x) (single buffer), W = WH + WL (fp16 split).
// out = A*WH + A*WL in fp32 accum -> error ~2^-11 elementwise, norm rel_err ~4e-4.
// Producer (R11): coalesced register loads + inverse-map scatter. Warp-specialized,
// persistent CTAs, double-buffered A, B resident.

#define NTHREADS 512
#define GRID     148
#define NTILES   2048
#define PITCH    272          // bytes per K-row (128 fp16 + 16B pad)

// smem byte offsets
#define SM_A0    0            // 64*272 = 17408
#define SM_A1    17408        // ends 34816
#define SM_B_HI  34816        // 256*272 = 69632, ends 104448
#define SM_B_LO  104448       // ends 174080
#define SM_INV   174080       // 2 bufs * 64 rows * 16B = 2048, ends 176128
#define SMEM_BYTES 176128

// Pre-split W (filled once by w_split): [n][k_new] fp16
__device__ __half g_Whi[256 * 128];
__device__ __half g_Wlo[256 * 128];

// K permutation: k_new = 14*u + f. u=0: query f (0..12). u=1..8: slot u-1,
// feature f, k_old = 13 + 13*(u-1) + f. f==13 or k_new>=126 -> zero.
__global__ void w_split(const float* __restrict__ W) {
    const int kn = blockIdx.x;       // 0..127
    const int n = threadIdx.x;       // 0..255
    float w = 0.0f;
    if (kn < 126) {
        const int u = kn / 14, f = kn % 14;
        if (f < 13) {
            const int ko = (u == 0) ? f : 13 + 13 * (u - 1) + f;
            w = W[ko * 256 + n];
        }
    }
    __half h = __float2half_rn(w);
    g_Whi[n * 128 + kn] = h;
    g_Wlo[n * 128 + kn] = __float2half_rn(w - __half2float(h));
}

static __device__ __forceinline__ uint32_t smem_u32(const void* p) {
    uint32_t a;
    asm("{ .reg .u64 t; cvta.to.shared.u64 t, %1; cvt.u32.u64 %0, t; }" : "=r"(a) : "l"(p));
    return a;
}
static __device__ __forceinline__ void bar_sync(int id, int cnt) {
    asm volatile("bar.sync %0, %1;" :: "r"(id), "r"(cnt) : "memory");
}
static __device__ __forceinline__ void bar_arrive(int id, int cnt) {
    asm volatile("bar.arrive %0, %1;" :: "r"(id), "r"(cnt) : "memory");
}
static __device__ __forceinline__ void ldsm_x4(uint32_t& r0, uint32_t& r1, uint32_t& r2,
                                               uint32_t& r3, uint32_t addr) {
    asm volatile("ldmatrix.sync.aligned.m8n8.x4.shared.b16 {%0,%1,%2,%3}, [%4];"
                 : "=r"(r0), "=r"(r1), "=r"(r2), "=r"(r3) : "r"(addr));
}
static __device__ __forceinline__ void mma_f16(float* c, const uint32_t* a,
                                               uint32_t b0, uint32_t b1) {
    asm volatile(
        "mma.sync.aligned.m16n8k16.row.col.f32.f16.f16.f32 "
        "{%0,%1,%2,%3}, {%4,%5,%6,%7}, {%8,%9}, {%0,%1,%2,%3};"
        : "+f"(c[0]), "+f"(c[1]), "+f"(c[2]), "+f"(c[3])
        : "r"(a[0]), "r"(a[1]), "r"(a[2]), "r"(a[3]), "r"(b0), "r"(b1));
}
// pack two floats to f16x2 (lo = v0, hi = v1)
static __device__ __forceinline__ uint32_t cvt2h(float v0, float v1) {
    uint32_t r;
    asm("cvt.rn.f16x2.f32 %0, %1, %2;" : "=r"(r) : "f"(v1), "f"(v0));
    return r;
}
// write 13 features (fp16, packed STS.32) at 4-aligned k0*2 (k0 = 14*u)
static __device__ __forceinline__ void write14h(char* a, int k0, const float* f) {
#pragma unroll
    for (int p = 0; p < 7; p++) {
        const float v0 = f[2 * p];
        const float v1 = (2 * p + 1 < 13) ? f[2 * p + 1] : 0.0f;
        *(uint32_t*)(a + k0 * 2 + p * 4) = cvt2h(v0, v1);
    }
}

__global__ __launch_bounds__(512, 1)
void mg_enc_ws(const float* __restrict__ qpos, const float* __restrict__ qdir,
               const float* __restrict__ qab,  const float* __restrict__ qcar,
               const float* __restrict__ qst,
               const float* __restrict__ apos, const float* __restrict__ adir,
               const float* __restrict__ aab,  const float* __restrict__ acar,
               const float* __restrict__ ast,
               const int*   __restrict__ color,
               const float* __restrict__ bias,
               float* __restrict__ out)
{
    extern __shared__ __align__(128) char smem[];
    const uint32_t sbase = smem_u32(smem);
    const int tid = threadIdx.x;

    if (tid >= 256) {
        // ======================= PRODUCER (warps 8..15) =======================
        const int tp = tid - 256;
        const int fr = tp >> 2, fp = tp & 3;    // feature duty: row fr, agents 4fp..4fp+3

        // zero-pad K rows 126,127 in both A buffers (once)
        if (tp < 128) {
            const int r = tp >> 1, kk = 126 + (tp & 1);
            const uint32_t o = r * PITCH + kk * 2;
            *(__half*)(smem + SM_A0 + o) = __half(0.0f);
            *(__half*)(smem + SM_A1 + o) = __half(0.0f);
        }

        int t = blockIdx.x;
        int4 c0, c1, c2, c3;
        if (tp < 64) {
            const int4* cp = (const int4*)(color + (size_t)(t * 64 + tp) * 16);
            c0 = cp[0]; c1 = cp[1]; c2 = cp[2]; c3 = cp[3];
        }

        for (int it = 0; t < NTILES; it++, t += GRID) {
            const int buf = it & 1;
            const int row0 = t * 64;

            // ---- coalesced feature loads for current tile (issue before waits) ----
            const size_t frow = (size_t)(row0 + fr);
            const float4 ap0 = *(const float4*)(apos + frow * 32 + fp * 8);
            const float4 ap1 = *(const float4*)(apos + frow * 32 + fp * 8 + 4);
            const float4 ad0 = *(const float4*)(adir + frow * 64 + fp * 16);
            const float4 ad1 = *(const float4*)(adir + frow * 64 + fp * 16 + 4);
            const float4 ad2 = *(const float4*)(adir + frow * 64 + fp * 16 + 8);
            const float4 ad3 = *(const float4*)(adir + frow * 64 + fp * 16 + 12);
            const float4 ab0 = *(const float4*)(aab  + frow * 32 + fp * 8);
            const float4 ab1 = *(const float4*)(aab  + frow * 32 + fp * 8 + 4);
            const float4 ac0 = *(const float4*)(acar + frow * 32 + fp * 8);
            const float4 ac1 = *(const float4*)(acar + frow * 32 + fp * 8 + 4);
            const float4 as0 = *(const float4*)(ast  + frow * 48 + fp * 12);
            const float4 as1 = *(const float4*)(ast  + frow * 48 + fp * 12 + 4);
            const float4 as2 = *(const float4*)(ast  + frow * 48 + fp * 12 + 8);

            // query loads (tp<64, row tp)
            float q[13];
            if (tp < 64) {
                const size_t row = (size_t)(row0 + tp);
                *(float2*)(q + 0) = *(const float2*)(qpos + row * 2);
                *(float4*)(q + 2) = *(const float4*)(qdir + row * 4);
                *(float2*)(q + 6) = *(const float2*)(qab  + row * 2);
                *(float2*)(q + 8) = *(const float2*)(qcar + row * 2);
                q[10] = qst[row * 3 + 0]; q[11] = qst[row * 3 + 1]; q[12] = qst[row * 3 + 2];
            }

            // ---- slot compute (regs only): inverse map + fill counts ----
            uint32_t invw[4] = {0xFFFFFFFFu, 0xFFFFFFFFu, 0xFFFFFFFFu, 0xFFFFFFFFu};
            int sg = 0, sy = 0;
            if (tp < 64) {
                int cols[16] = { c0.x, c0.y, c0.z, c0.w, c1.x, c1.y, c1.z, c1.w,
                                 c2.x, c2.y, c2.z, c2.w, c3.x, c3.y, c3.z, c3.w };
#pragma unroll
                for (int n = 0; n < 16; n++) {
                    const int c = cols[n];
                    int s = -1;
                    if (c == 5) { if (sg < 4) s = sg; sg++; }
                    else if (c == 4) { if (sy < 4) s = 4 + sy; sy++; }
                    if (s >= 0) {
                        invw[n >> 2] &= ~(0xFFu << (8 * (n & 3)));
                        invw[n >> 2] |= (uint32_t)s << (8 * (n & 3));
                    }
                }
            }

            if (it >= 2) bar_sync(3 + buf, 512);              // wait buf free

            // store inverse map (16B per row)
            if (tp < 64)
                *(uint4*)(smem + SM_INV + buf * 1024 + tp * 16) =
                    make_uint4(invw[0], invw[1], invw[2], invw[3]);
            bar_sync(5, 256);                                  // inv visible to producers

            // prefetch next tile's color rows
            const int tn = t + GRID;
            if (tp < 64 && tn < NTILES) {
                const int4* cp = (const int4*)(color + (size_t)(tn * 64 + tp) * 16);
                c0 = cp[0]; c1 = cp[1]; c2 = cp[2]; c3 = cp[3];
            }

            char* const aB = smem + (buf ? SM_A1 : SM_A0);

            // slot threads: query unit + zero-fill empty slots (disjoint from agents)
            if (tp < 64) {
                char* a = aB + tp * PITCH;
                write14h(a, 0, q);
#pragma unroll
                for (int s = 0; s < 8; s++) {
                    const bool empty = (s < 4) ? (s >= sg) : (s - 4 >= sy);
                    if (empty) {
                        const int k0 = 14 * (s + 1);
#pragma unroll
                        for (int p7 = 0; p7 < 7; p7++)
                            *(uint32_t*)(a + k0 * 2 + p7 * 4) = 0u;
                    }
                }
            }

            // agent scatter from registers via inverse map
            {
                float fa[4][13];
                fa[0][0]=ap0.x; fa[0][1]=ap0.y; fa[1][0]=ap0.z; fa[1][1]=ap0.w;
                fa[2][0]=ap1.x; fa[2][1]=ap1.y; fa[3][0]=ap1.z; fa[3][1]=ap1.w;
                fa[0][2]=ad0.x; fa[0][3]=ad0.y; fa[0][4]=ad0.z; fa[0][5]=ad0.w;
                fa[1][2]=ad1.x; fa[1][3]=ad1.y; fa[1][4]=ad1.z; fa[1][5]=ad1.w;
                fa[2][2]=ad2.x; fa[2][3]=ad2.y; fa[2][4]=ad2.z; fa[2][5]=ad2.w;
                fa[3][2]=ad3.x; fa[3][3]=ad3.y; fa[3][4]=ad3.z; fa[3][5]=ad3.w;
                fa[0][6]=ab0.x; fa[0][7]=ab0.y; fa[1][6]=ab0.z; fa[1][7]=ab0.w;
                fa[2][6]=ab1.x; fa[2][7]=ab1.y; fa[3][6]=ab1.z; fa[3][7]=ab1.w;
                fa[0][8]=ac0.x; fa[0][9]=ac0.y; fa[1][8]=ac0.z; fa[1][9]=ac0.w;
                fa[2][8]=ac1.x; fa[2][9]=ac1.y; fa[3][8]=ac1.z; fa[3][9]=ac1.w;
                fa[0][10]=as0.x; fa[0][11]=as0.y; fa[0][12]=as0.z;
                fa[1][10]=as0.w; fa[1][11]=as1.x; fa[1][12]=as1.y;
                fa[2][10]=as1.z; fa[2][11]=as1.w; fa[2][12]=as2.x;
                fa[3][10]=as2.y; fa[3][11]=as2.z; fa[3][12]=as2.w;

                const uint32_t iw =
                    *(const uint32_t*)(smem + SM_INV + buf * 1024 + fr * 16 + fp * 4);
                char* a = aB + fr * PITCH;
#pragma unroll
                for (int i = 0; i < 4; i++) {
                    const uint32_t b = (iw >> (8 * i)) & 0xFFu;
                    if (b != 0xFFu)
                        write14h(a, 14 * ((int)b + 1), fa[i]);
                }
            }
            bar_arrive(1 + buf, 512);                          // A[buf] ready
        }
    } else {
        // ======================= CONSUMER (warps 0..7) =======================
        const int wid = tid >> 5, lid = tid & 31;

        // B tiles: copy pre-split fp16 W into smem (once)
#pragma unroll
        for (int it = 0; it < 16; it++) {
            const int idx = it * 256 + tid;
            const int n = idx >> 4, c = idx & 15;
            *(uint4*)(smem + SM_B_HI + n * PITCH + c * 16) =
                *(const uint4*)((const char*)g_Whi + n * 256 + c * 16);
            *(uint4*)(smem + SM_B_LO + n * PITCH + c * 16) =
                *(const uint4*)((const char*)g_Wlo + n * 256 + c * 16);
        }

        const int wm = wid >> 2, wn = wid & 3;   // 2 x 4 warp grid, warp tile 32x64
        const uint32_t lrow = lid & 15, lhalf = (uint32_t)lid >> 4;
        const uint32_t a_lane = (wm * 32 + lrow) * PITCH + lhalf * 16;
        const uint32_t b_lane = (wn * 64 + lrow) * PITCH + lhalf * 16;
        const uint32_t BHb = sbase + SM_B_HI + b_lane;
        const uint32_t BLb = sbase + SM_B_LO + b_lane;

        float be[8], bo[8];
#pragma unroll
        for (int nt = 0; nt < 8; nt++) {
            const int c = wn * 64 + (lid & 3) * 2 + nt * 8;
            be[nt] = bias[c];
            bo[nt] = bias[c + 1];
        }

        int t = blockIdx.x;
        for (int it = 0; t < NTILES; it++, t += GRID) {
            const int buf = it & 1;
            bar_sync(1 + buf, 512);                            // wait A[buf] ready

            const uint32_t Ab = sbase + (buf ? SM_A1 : SM_A0) + a_lane;

            float acc[2][8][4];
#pragma unroll
            for (int mt = 0; mt < 2; mt++)
#pragma unroll
                for (int nt = 0; nt < 8; nt++)
#pragma unroll
                    for (int e = 0; e < 4; e++) acc[mt][nt][e] = 0.0f;

            // 2-pass k-loop: A loaded once; A*BH then A*BL (BL reuses b regs)
#pragma unroll 2
            for (int ks = 0; ks < 8; ks++) {
                const uint32_t koff = ks * 32;
                uint32_t a[2][4], b[4][4];
#pragma unroll
                for (int mt = 0; mt < 2; mt++)
                    ldsm_x4(a[mt][0], a[mt][1], a[mt][2], a[mt][3],
                            Ab + mt * (16 * PITCH) + koff);
#pragma unroll
                for (int nb = 0; nb < 4; nb++)
                    ldsm_x4(b[nb][0], b[nb][1], b[nb][2], b[nb][3],
                            BHb + nb * (16 * PITCH) + koff);
#pragma unroll
                for (int mt = 0; mt < 2; mt++)
#pragma unroll
                    for (int nb = 0; nb < 4; nb++) {
                        mma_f16(acc[mt][nb * 2 + 0], a[mt], b[nb][0], b[nb][2]);
                        mma_f16(acc[mt][nb * 2 + 1], a[mt], b[nb][1], b[nb][3]);
                    }
#pragma unroll
                for (int nb = 0; nb < 4; nb++)
                    ldsm_x4(b[nb][0], b[nb][1], b[nb][2], b[nb][3],
                            BLb + nb * (16 * PITCH) + koff);
#pragma unroll
                for (int mt = 0; mt < 2; mt++)
#pragma unroll
                    for (int nb = 0; nb < 4; nb++) {
                        mma_f16(acc[mt][nb * 2 + 0], a[mt], b[nb][0], b[nb][2]);
                        mma_f16(acc[mt][nb * 2 + 1], a[mt], b[nb][1], b[nb][3]);
                    }
            }
            bar_arrive(3 + buf, 512);                          // A[buf] free

            // epilogue: bias + relu + direct float2 stores (overlaps producer)
            const int rbase = t * 64 + wm * 32 + (lid >> 2);
            const int cbase = wn * 64 + (lid & 3) * 2;
#pragma unroll
            for (int mt = 0; mt < 2; mt++) {
#pragma unroll
                for (int nt = 0; nt < 8; nt++) {
                    const int c = cbase + nt * 8;
                    float2 v0, v1;
                    v0.x = fmaxf(acc[mt][nt][0] + be[nt], 0.0f);
                    v0.y = fmaxf(acc[mt][nt][1] + bo[nt], 0.0f);
                    v1.x = fmaxf(acc[mt][nt][2] + be[nt], 0.0f);
                    v1.y = fmaxf(acc[mt][nt][3] + bo[nt], 0.0f);
                    const size_t r0 = (size_t)(rbase + mt * 16);
                    *(float2*)(out + r0 * 256 + c)       = v0;
                    *(float2*)(out + (r0 + 8) * 256 + c) = v1;
                }
            }
        }
    }
}

extern "C" void kernel_launch(void* const* d_in, const int* in_sizes, int n_in,
                              void* d_out, int out_size)
{
    const float* qpos  = (const float*)d_in[0];
    const float* qdir  = (const float*)d_in[1];
    const float* qab   = (const float*)d_in[2];
    const float* qcar  = (const float*)d_in[3];
    const float* qst   = (const float*)d_in[4];
    const float* apos  = (const float*)d_in[5];
    const float* adir  = (const float*)d_in[6];
    const float* aab   = (const float*)d_in[7];
    const float* acar  = (const float*)d_in[8];
    const float* ast   = (const float*)d_in[9];
    const int*   color = (const int*)  d_in[10];
    const float* W     = (const float*)d_in[11];
    const float* bias  = (const float*)d_in[12];
    float* out = (float*)d_out;

    w_split<<<128, 256>>>(W);

    cudaFuncSetAttribute(mg_enc_ws,
                         cudaFuncAttributeMaxDynamicSharedMemorySize, SMEM_BYTES);
    mg_enc_ws<<<GRID, NTHREADS, SMEM_BYTES>>>(
        qpos, qdir, qab, qcar, qst,
        apos, adir, aab, acar, ast,
        color, bias, out);
}

// round 17
// speedup vs baseline: 1.6234x; 1.2870x over previous
#include <cuda_runtime.h>
#include <cuda_fp16.h>
#include <cstdint>

// MultiGridAgentEncoder: fused slot-gather + relu(x @ W + b)
// R16: plain fp16 GEMM (A and W both single fp16, fp32 accumulate).
// Measured rel_err with A-only truncation was 2.07e-4; W truncation adds an
// independent equal term -> ~2.9e-4 expected, margin 3.4x to the 1e-3 gate.
// Warp-specialized persistent kernel: 8 producer warps (coalesced register
// loads + inverse-map scatter) / 8 consumer warps (HMMA), double-buffered A,
// B resident in smem.

#define NTHREADS 512
#define GRID     148
#define NTILES   2048
#define PITCH    272          // bytes per K-row (128 fp16 + 16B pad)

// smem byte offsets
#define SM_A0    0            // 64*272 = 17408
#define SM_A1    17408        // ends 34816
#define SM_B     34816        // 256*272 = 69632, ends 104448
#define SM_INV   104448       // 2 bufs * 64 rows * 16B = 2048, ends 106496
#define SMEM_BYTES 106496

// Pre-converted W (filled once by w_split): [n][k_new] fp16
__device__ __half g_W[256 * 128];

// K permutation: k_new = 14*u + f. u=0: query f (0..12). u=1..8: slot u-1,
// feature f, k_old = 13 + 13*(u-1) + f. f==13 or k_new>=126 -> zero.
__global__ void w_split(const float* __restrict__ W) {
    const int kn = blockIdx.x;       // 0..127
    const int n = threadIdx.x;       // 0..255
    float w = 0.0f;
    if (kn < 126) {
        const int u = kn / 14, f = kn % 14;
        if (f < 13) {
            const int ko = (u == 0) ? f : 13 + 13 * (u - 1) + f;
            w = W[ko * 256 + n];
        }
    }
    g_W[n * 128 + kn] = __float2half_rn(w);
}

static __device__ __forceinline__ uint32_t smem_u32(const void* p) {
    uint32_t a;
    asm("{ .reg .u64 t; cvta.to.shared.u64 t, %1; cvt.u32.u64 %0, t; }" : "=r"(a) : "l"(p));
    return a;
}
static __device__ __forceinline__ void bar_sync(int id, int cnt) {
    asm volatile("bar.sync %0, %1;" :: "r"(id), "r"(cnt) : "memory");
}
static __device__ __forceinline__ void bar_arrive(int id, int cnt) {
    asm volatile("bar.arrive %0, %1;" :: "r"(id), "r"(cnt) : "memory");
}
static __device__ __forceinline__ void ldsm_x4(uint32_t& r0, uint32_t& r1, uint32_t& r2,
                                               uint32_t& r3, uint32_t addr) {
    asm volatile("ldmatrix.sync.aligned.m8n8.x4.shared.b16 {%0,%1,%2,%3}, [%4];"
                 : "=r"(r0), "=r"(r1), "=r"(r2), "=r"(r3) : "r"(addr));
}
static __device__ __forceinline__ void mma_f16(float* c, const uint32_t* a,
                                               uint32_t b0, uint32_t b1) {
    asm volatile(
        "mma.sync.aligned.m16n8k16.row.col.f32.f16.f16.f32 "
        "{%0,%1,%2,%3}, {%4,%5,%6,%7}, {%8,%9}, {%0,%1,%2,%3};"
        : "+f"(c[0]), "+f"(c[1]), "+f"(c[2]), "+f"(c[3])
        : "r"(a[0]), "r"(a[1]), "r"(a[2]), "r"(a[3]), "r"(b0), "r"(b1));
}
// pack two floats to f16x2 (lo = v0, hi = v1)
static __device__ __forceinline__ uint32_t cvt2h(float v0, float v1) {
    uint32_t r;
    asm("cvt.rn.f16x2.f32 %0, %1, %2;" : "=r"(r) : "f"(v1), "f"(v0));
    return r;
}
// write 13 features (fp16, packed STS.32) at 4-aligned k0*2 (k0 = 14*u)
static __device__ __forceinline__ void write14h(char* a, int k0, const float* f) {
#pragma unroll
    for (int p = 0; p < 7; p++) {
        const float v0 = f[2 * p];
        const float v1 = (2 * p + 1 < 13) ? f[2 * p + 1] : 0.0f;
        *(uint32_t*)(a + k0 * 2 + p * 4) = cvt2h(v0, v1);
    }
}

__global__ __launch_bounds__(512, 1)
void mg_enc_ws(const float* __restrict__ qpos, const float* __restrict__ qdir,
               const float* __restrict__ qab,  const float* __restrict__ qcar,
               const float* __restrict__ qst,
               const float* __restrict__ apos, const float* __restrict__ adir,
               const float* __restrict__ aab,  const float* __restrict__ acar,
               const float* __restrict__ ast,
               const int*   __restrict__ color,
               const float* __restrict__ bias,
               float* __restrict__ out)
{
    extern __shared__ __align__(128) char smem[];
    const uint32_t sbase = smem_u32(smem);
    const int tid = threadIdx.x;

    if (tid >= 256) {
        // ======================= PRODUCER (warps 8..15) =======================
        const int tp = tid - 256;
        const int fr = tp >> 2, fp = tp & 3;    // feature duty: row fr, agents 4fp..4fp+3

        // zero-pad K rows 126,127 in both A buffers (once)
        if (tp < 128) {
            const int r = tp >> 1, kk = 126 + (tp & 1);
            const uint32_t o = r * PITCH + kk * 2;
            *(__half*)(smem + SM_A0 + o) = __half(0.0f);
            *(__half*)(smem + SM_A1 + o) = __half(0.0f);
        }

        int t = blockIdx.x;
        int4 c0, c1, c2, c3;
        if (tp < 64) {
            const int4* cp = (const int4*)(color + (size_t)(t * 64 + tp) * 16);
            c0 = cp[0]; c1 = cp[1]; c2 = cp[2]; c3 = cp[3];
        }

        for (int it = 0; t < NTILES; it++, t += GRID) {
            const int buf = it & 1;
            const int row0 = t * 64;

            // ---- coalesced feature loads for current tile (issue before waits) ----
            const size_t frow = (size_t)(row0 + fr);
            const float4 ap0 = *(const float4*)(apos + frow * 32 + fp * 8);
            const float4 ap1 = *(const float4*)(apos + frow * 32 + fp * 8 + 4);
            const float4 ad0 = *(const float4*)(adir + frow * 64 + fp * 16);
            const float4 ad1 = *(const float4*)(adir + frow * 64 + fp * 16 + 4);
            const float4 ad2 = *(const float4*)(adir + frow * 64 + fp * 16 + 8);
            const float4 ad3 = *(const float4*)(adir + frow * 64 + fp * 16 + 12);
            const float4 ab0 = *(const float4*)(aab  + frow * 32 + fp * 8);
            const float4 ab1 = *(const float4*)(aab  + frow * 32 + fp * 8 + 4);
            const float4 ac0 = *(const float4*)(acar + frow * 32 + fp * 8);
            const float4 ac1 = *(const float4*)(acar + frow * 32 + fp * 8 + 4);
            const float4 as0 = *(const float4*)(ast  + frow * 48 + fp * 12);
            const float4 as1 = *(const float4*)(ast  + frow * 48 + fp * 12 + 4);
            const float4 as2 = *(const float4*)(ast  + frow * 48 + fp * 12 + 8);

            // query loads (tp<64, row tp)
            float q[13];
            if (tp < 64) {
                const size_t row = (size_t)(row0 + tp);
                *(float2*)(q + 0) = *(const float2*)(qpos + row * 2);
                *(float4*)(q + 2) = *(const float4*)(qdir + row * 4);
                *(float2*)(q + 6) = *(const float2*)(qab  + row * 2);
                *(float2*)(q + 8) = *(const float2*)(qcar + row * 2);
                q[10] = qst[row * 3 + 0]; q[11] = qst[row * 3 + 1]; q[12] = qst[row * 3 + 2];
            }

            // ---- slot compute (regs only): inverse map + fill counts ----
            uint32_t invw[4] = {0xFFFFFFFFu, 0xFFFFFFFFu, 0xFFFFFFFFu, 0xFFFFFFFFu};
            int sg = 0, sy = 0;
            if (tp < 64) {
                int cols[16] = { c0.x, c0.y, c0.z, c0.w, c1.x, c1.y, c1.z, c1.w,
                                 c2.x, c2.y, c2.z, c2.w, c3.x, c3.y, c3.z, c3.w };
#pragma unroll
                for (int n = 0; n < 16; n++) {
                    const int c = cols[n];
                    int s = -1;
                    if (c == 5) { if (sg < 4) s = sg; sg++; }
                    else if (c == 4) { if (sy < 4) s = 4 + sy; sy++; }
                    if (s >= 0) {
                        invw[n >> 2] &= ~(0xFFu << (8 * (n & 3)));
                        invw[n >> 2] |= (uint32_t)s << (8 * (n & 3));
                    }
                }
            }

            if (it >= 2) bar_sync(3 + buf, 512);              // wait buf free

            // store inverse map (16B per row)
            if (tp < 64)
                *(uint4*)(smem + SM_INV + buf * 1024 + tp * 16) =
                    make_uint4(invw[0], invw[1], invw[2], invw[3]);
            bar_sync(5, 256);                                  // inv visible to producers

            // prefetch next tile's color rows
            const int tn = t + GRID;
            if (tp < 64 && tn < NTILES) {
                const int4* cp = (const int4*)(color + (size_t)(tn * 64 + tp) * 16);
                c0 = cp[0]; c1 = cp[1]; c2 = cp[2]; c3 = cp[3];
            }

            char* const aB = smem + (buf ? SM_A1 : SM_A0);

            // slot threads: query unit + zero-fill empty slots (disjoint from agents)
            if (tp < 64) {
                char* a = aB + tp * PITCH;
                write14h(a, 0, q);
#pragma unroll
                for (int s = 0; s < 8; s++) {
                    const bool empty = (s < 4) ? (s >= sg) : (s - 4 >= sy);
                    if (empty) {
                        const int k0 = 14 * (s + 1);
#pragma unroll
                        for (int p7 = 0; p7 < 7; p7++)
                            *(uint32_t*)(a + k0 * 2 + p7 * 4) = 0u;
                    }
                }
            }

            // agent scatter from registers via inverse map
            {
                float fa[4][13];
                fa[0][0]=ap0.x; fa[0][1]=ap0.y; fa[1][0]=ap0.z; fa[1][1]=ap0.w;
                fa[2][0]=ap1.x; fa[2][1]=ap1.y; fa[3][0]=ap1.z; fa[3][1]=ap1.w;
                fa[0][2]=ad0.x; fa[0][3]=ad0.y; fa[0][4]=ad0.z; fa[0][5]=ad0.w;
                fa[1][2]=ad1.x; fa[1][3]=ad1.y; fa[1][4]=ad1.z; fa[1][5]=ad1.w;
                fa[2][2]=ad2.x; fa[2][3]=ad2.y; fa[2][4]=ad2.z; fa[2][5]=ad2.w;
                fa[3][2]=ad3.x; fa[3][3]=ad3.y; fa[3][4]=ad3.z; fa[3][5]=ad3.w;
                fa[0][6]=ab0.x; fa[0][7]=ab0.y; fa[1][6]=ab0.z; fa[1][7]=ab0.w;
                fa[2][6]=ab1.x; fa[2][7]=ab1.y; fa[3][6]=ab1.z; fa[3][7]=ab1.w;
                fa[0][8]=ac0.x; fa[0][9]=ac0.y; fa[1][8]=ac0.z; fa[1][9]=ac0.w;
                fa[2][8]=ac1.x; fa[2][9]=ac1.y; fa[3][8]=ac1.z; fa[3][9]=ac1.w;
                fa[0][10]=as0.x; fa[0][11]=as0.y; fa[0][12]=as0.z;
                fa[1][10]=as0.w; fa[1][11]=as1.x; fa[1][12]=as1.y;
                fa[2][10]=as1.z; fa[2][11]=as1.w; fa[2][12]=as2.x;
                fa[3][10]=as2.y; fa[3][11]=as2.z; fa[3][12]=as2.w;

                const uint32_t iw =
                    *(const uint32_t*)(smem + SM_INV + buf * 1024 + fr * 16 + fp * 4);
                char* a = aB + fr * PITCH;
#pragma unroll
                for (int i = 0; i < 4; i++) {
                    const uint32_t b = (iw >> (8 * i)) & 0xFFu;
                    if (b != 0xFFu)
                        write14h(a, 14 * ((int)b + 1), fa[i]);
                }
            }
            bar_arrive(1 + buf, 512);                          // A[buf] ready
        }
    } else {
        // ======================= CONSUMER (warps 0..7) =======================
        const int wid = tid >> 5, lid = tid & 31;

        // B tile: copy fp16 W into smem (once)
#pragma unroll
        for (int it = 0; it < 16; it++) {
            const int idx = it * 256 + tid;
            const int n = idx >> 4, c = idx & 15;
            *(uint4*)(smem + SM_B + n * PITCH + c * 16) =
                *(const uint4*)((const char*)g_W + n * 256 + c * 16);
        }

        const int wm = wid >> 2, wn = wid & 3;   // 2 x 4 warp grid, warp tile 32x64
        const uint32_t lrow = lid & 15, lhalf = (uint32_t)lid >> 4;
        const uint32_t a_lane = (wm * 32 + lrow) * PITCH + lhalf * 16;
        const uint32_t b_lane = (wn * 64 + lrow) * PITCH + lhalf * 16;
        const uint32_t Bb = sbase + SM_B + b_lane;

        float be[8], bo[8];
#pragma unroll
        for (int nt = 0; nt < 8; nt++) {
            const int c = wn * 64 + (lid & 3) * 2 + nt * 8;
            be[nt] = bias[c];
            bo[nt] = bias[c + 1];
        }

        int t = blockIdx.x;
        for (int it = 0; t < NTILES; it++, t += GRID) {
            const int buf = it & 1;
            bar_sync(1 + buf, 512);                            // wait A[buf] ready

            const uint32_t Ab = sbase + (buf ? SM_A1 : SM_A0) + a_lane;

            float acc[2][8][4];
#pragma unroll
            for (int mt = 0; mt < 2; mt++)
#pragma unroll
                for (int nt = 0; nt < 8; nt++)
#pragma unroll
                    for (int e = 0; e < 4; e++) acc[mt][nt][e] = 0.0f;

            // single-pass k-loop: A and B each loaded once per k-step
#pragma unroll
            for (int ks = 0; ks < 8; ks++) {
                const uint32_t koff = ks * 32;
                uint32_t a[2][4], b[4][4];
#pragma unroll
                for (int mt = 0; mt < 2; mt++)
                    ldsm_x4(a[mt][0], a[mt][1], a[mt][2], a[mt][3],
                            Ab + mt * (16 * PITCH) + koff);
#pragma unroll
                for (int nb = 0; nb < 4; nb++)
                    ldsm_x4(b[nb][0], b[nb][1], b[nb][2], b[nb][3],
                            Bb + nb * (16 * PITCH) + koff);
#pragma unroll
                for (int mt = 0; mt < 2; mt++)
#pragma unroll
                    for (int nb = 0; nb < 4; nb++) {
                        mma_f16(acc[mt][nb * 2 + 0], a[mt], b[nb][0], b[nb][2]);
                        mma_f16(acc[mt][nb * 2 + 1], a[mt], b[nb][1], b[nb][3]);
                    }
            }
            bar_arrive(3 + buf, 512);                          // A[buf] free

            // epilogue: bias + relu + direct float2 stores (overlaps producer)
            const int rbase = t * 64 + wm * 32 + (lid >> 2);
            const int cbase = wn * 64 + (lid & 3) * 2;
#pragma unroll
            for (int mt = 0; mt < 2; mt++) {
#pragma unroll
                for (int nt = 0; nt < 8; nt++) {
                    const int c = cbase + nt * 8;
                    float2 v0, v1;
                    v0.x = fmaxf(acc[mt][nt][0] + be[nt], 0.0f);
                    v0.y = fmaxf(acc[mt][nt][1] + bo[nt], 0.0f);
                    v1.x = fmaxf(acc[mt][nt][2] + be[nt], 0.0f);
                    v1.y = fmaxf(acc[mt][nt][3] + bo[nt], 0.0f);
                    const size_t r0 = (size_t)(rbase + mt * 16);
                    *(float2*)(out + r0 * 256 + c)       = v0;
                    *(float2*)(out + (r0 + 8) * 256 + c) = v1;
                }
            }
        }
    }
}

extern "C" void kernel_launch(void* const* d_in, const int* in_sizes, int n_in,
                              void* d_out, int out_size)
{
    const float* qpos  = (const float*)d_in[0];
    const float* qdir  = (const float*)d_in[1];
    const float* qab   = (const float*)d_in[2];
    const float* qcar  = (const float*)d_in[3];
    const float* qst   = (const float*)d_in[4];
    const float* apos  = (const float*)d_in[5];
    const float* adir  = (const float*)d_in[6];
    const float* aab   = (const float*)d_in[7];
    const float* acar  = (const float*)d_in[8];
    const float* ast   = (const float*)d_in[9];
    const int*   color = (const int*)  d_in[10];
    const float* W     = (const float*)d_in[11];
    const float* bias  = (const float*)d_in[12];
    float* out = (float*)d_out;

    w_split<<<128, 256>>>(W);

    cudaFuncSetAttribute(mg_enc_ws,
                         cudaFuncAttributeMaxDynamicSharedMemorySize, SMEM_BYTES);
    mg_enc_ws<<<GRID, NTHREADS, SMEM_BYTES>>>(
        qpos, qdir, qab, qcar, qst,
        apos, adir, aab, acar, ast,
        color, bias, out);
}